// round 15
// baseline (speedup 1.0000x reference)
#include <cuda_runtime.h>
#include <math.h>
#include <math_constants.h>
#include <cstdint>

// Problem shape (fixed by the reference)
constexpr int B_ = 8;
constexpr int T_ = 2048;
constexpr int E_ = 1024;
constexpr int H_ = 64;
constexpr int MT = B_ * T_;   // 16384 rows

// ---------------------------------------------------------------------------
// Device globals (no allocs allowed)
// ---------------------------------------------------------------------------
__device__ __align__(16) uint32_t g_wqh[64 * 512];
__device__ __align__(16) uint32_t g_wql[64 * 512];
__device__ __align__(16) uint32_t g_wkh[64 * 512];
__device__ __align__(16) uint32_t g_wkl[64 * 512];
__device__ __align__(16) float    g_wv [64 * 1024];   // tf32-rounded

__device__ __align__(16) uint32_t g_qbh[MT * 32];
__device__ __align__(16) uint32_t g_qbl[MT * 32];
__device__ __align__(16) uint32_t g_kbh[MT * 32];
__device__ __align__(16) uint32_t g_kbl[MT * 32];
// V^T, fp16 packed along keys: g_vt[(b*64 + h)*1024 + w] = v[b][2w..2w+1][h]
__device__ __align__(16) uint32_t g_vt [B_ * 64 * 1024];

// Split-KV scratch: 1024 units (b 0..7, jq 0..31, chunk 0..3)
__device__ __align__(16) float g_po[1024 * 4096];
__device__ float g_pm[1024 * 64];
__device__ float g_pl[1024 * 64];

// ===========================================================================
// Baseline-PTX helpers (all valid at compute_103)
// ===========================================================================
__device__ __forceinline__ uint32_t smem_u32(const void* p) {
    uint32_t a;
    asm("{ .reg .u64 t; cvta.to.shared.u64 t, %1; cvt.u32.u64 %0, t; }"
        : "=r"(a) : "l"(p));
    return a;
}
__device__ __forceinline__ float tf32r(float v) {
    uint32_t u;
    asm("cvt.rna.tf32.f32 %0, %1;" : "=r"(u) : "f"(v));
    return __uint_as_float(u);
}
__device__ __forceinline__ float ex2f(float x) {
    float r;
    asm("ex2.approx.f32 %0, %1;" : "=f"(r) : "f"(x));
    return r;
}
// Pack float2 -> bf16x2 hi word + bf16x2 lo word (hi = rn(v), lo = rn(v-hi))
__device__ __forceinline__ void bsplit2(float2 f, uint32_t& h, uint32_t& l) {
    asm("cvt.rn.bf16x2.f32 %0, %1, %2;" : "=r"(h) : "f"(f.y), "f"(f.x));
    float hx = __uint_as_float(h << 16);
    float hy = __uint_as_float(h & 0xffff0000u);
    asm("cvt.rn.bf16x2.f32 %0, %1, %2;" : "=r"(l) : "f"(f.y - hy), "f"(f.x - hx));
}
// Pack (hi, lo) floats -> fp16x2 word (low half = lo)
__device__ __forceinline__ uint32_t f16x2(float hi, float lo) {
    uint32_t r;
    asm("cvt.rn.f16x2.f32 %0, %1, %2;" : "=r"(r) : "f"(hi), "f"(lo));
    return r;
}
// ldmatrix: 4x (8x8 b16) tiles, no transpose
__device__ __forceinline__ void ldm4(uint32_t& r0, uint32_t& r1,
                                     uint32_t& r2, uint32_t& r3, uint32_t addr) {
    asm volatile("ldmatrix.sync.aligned.m8n8.x4.shared.b16 {%0,%1,%2,%3}, [%4];"
        : "=r"(r0), "=r"(r1), "=r"(r2), "=r"(r3) : "r"(addr));
}
// D += A(16x16) * B(16x8), bf16 inputs, fp32 accum
__device__ __forceinline__ void mma16b(float* c,
                                       uint32_t a0, uint32_t a1, uint32_t a2, uint32_t a3,
                                       uint32_t b0, uint32_t b1) {
    asm volatile(
        "mma.sync.aligned.m16n8k16.row.col.f32.bf16.bf16.f32 "
        "{%0,%1,%2,%3}, {%4,%5,%6,%7}, {%8,%9}, {%0,%1,%2,%3};"
        : "+f"(c[0]), "+f"(c[1]), "+f"(c[2]), "+f"(c[3])
        : "r"(a0), "r"(a1), "r"(a2), "r"(a3), "r"(b0), "r"(b1));
}
// D += A(16x16) * B(16x8), fp16 inputs, fp32 accum
__device__ __forceinline__ void mma16f(float* c,
                                       uint32_t a0, uint32_t a1, uint32_t a2, uint32_t a3,
                                       uint32_t b0, uint32_t b1) {
    asm volatile(
        "mma.sync.aligned.m16n8k16.row.col.f32.f16.f16.f32 "
        "{%0,%1,%2,%3}, {%4,%5,%6,%7}, {%8,%9}, {%0,%1,%2,%3};"
        : "+f"(c[0]), "+f"(c[1]), "+f"(c[2]), "+f"(c[3])
        : "r"(a0), "r"(a1), "r"(a2), "r"(a3), "r"(b0), "r"(b1));
}
// D += A(16x8) * B(8x8), tf32 inputs, fp32 accum
__device__ __forceinline__ void mma8(float* c,
                                     uint32_t a0, uint32_t a1, uint32_t a2, uint32_t a3,
                                     uint32_t b0, uint32_t b1) {
    asm volatile(
        "mma.sync.aligned.m16n8k8.row.col.f32.tf32.tf32.f32 "
        "{%0,%1,%2,%3}, {%4,%5,%6,%7}, {%8,%9}, {%0,%1,%2,%3};"
        : "+f"(c[0]), "+f"(c[1]), "+f"(c[2]), "+f"(c[3])
        : "r"(a0), "r"(a1), "r"(a2), "r"(a3), "r"(b0), "r"(b1));
}
__device__ __forceinline__ uint32_t fu(float v) { return __float_as_uint(v); }

#define CP16(d, s)  asm volatile("cp.async.ca.shared.global [%0], [%1], 16;" :: "r"(d), "l"(s))
#define CP_COMMIT() asm volatile("cp.async.commit_group;" ::: "memory")
#define CP_WAIT0()  asm volatile("cp.async.wait_group 0;" ::: "memory")
#define CP_WAIT1()  asm volatile("cp.async.wait_group 1;" ::: "memory")

// ===========================================================================
// Kernel 0: weight prep. Wq/Wk -> packed bf16 hi/lo; Wv -> tf32-rounded.
// ===========================================================================
__global__ void prep_kernel(const float* __restrict__ Wq,
                            const float* __restrict__ Wk,
                            const float* __restrict__ Wv)
{
    const int r = blockIdx.x, mat = blockIdx.y, tid = threadIdx.x;
    if (mat < 2) {
        const float* W = mat ? Wk : Wq;
        uint32_t* dh = mat ? g_wkh : g_wqh;
        uint32_t* dl = mat ? g_wkl : g_wql;
        // 256 float4 per row; each thread does one
        if (tid < 256) {
            float4 f = *reinterpret_cast<const float4*>(&W[r * 1024 + 4 * tid]);
            uint32_t h0, l0, h1, l1;
            bsplit2(make_float2(f.x, f.y), h0, l0);
            bsplit2(make_float2(f.z, f.w), h1, l1);
            *reinterpret_cast<uint2*>(&dh[r * 512 + 2 * tid]) = make_uint2(h0, h1);
            *reinterpret_cast<uint2*>(&dl[r * 512 + 2 * tid]) = make_uint2(l0, l1);
        }
    } else {
        float4 f = *reinterpret_cast<const float4*>(&Wv[r * 1024 + 4 * tid]);
        float4 o = make_float4(tf32r(f.x), tf32r(f.y), tf32r(f.z), tf32r(f.w));
        *reinterpret_cast<float4*>(&g_wv[r * 1024 + 4 * tid]) = o;
    }
}

// ===========================================================================
// Kernel 1: merged QKV projection — 192 threads (6 warps: 2Q/2K/2V).
// (round-13 proven single-wave structure)
// ===========================================================================
constexpr int XSTR = 40;
constexpr int WSTR = 20;
constexpr int VSTR = 36;
constexpr uint32_t OX   = 0;
constexpr uint32_t OWH0 = 10240;
constexpr uint32_t OWL0 = 15360;
constexpr uint32_t OWH1 = 20480;
constexpr uint32_t OWL1 = 25600;
constexpr uint32_t OWV  = 30720;
constexpr uint32_t QSTG = 39936;
constexpr uint32_t QKV_SMEM = 2 * QSTG;   // 79872 bytes

__global__ __launch_bounds__(192, 2) void qkv_kernel(const float* __restrict__ x)
{
    extern __shared__ char sm8[];
    const uint32_t sb = smem_u32(sm8);
    const int tid  = threadIdx.x;
    const int wid  = tid >> 5, lane = tid & 31;
    const int g = lane >> 2, c = lane & 3;
    const int mat = wid >> 1;          // 0=Q, 1=K, 2=V
    const int rb0 = (wid & 1) * 32;    // warp row base (2 sets of 16)
    const int m0  = blockIdx.x * 64;
    const uint32_t loffw = (uint32_t)(((lane & 7) * WSTR + (lane >> 3) * 4) * 4);

    auto issue = [&](int ch, int st) {
        const uint32_t s0 = sb + (uint32_t)st * QSTG;
        const int k0 = ch * 32;
        for (int i = tid; i < 2048; i += 192) {
            if (i < 512) {
                int r = i >> 3, sg = i & 7;
                CP16(s0 + OX + (uint32_t)(r * XSTR + sg * 4) * 4,
                     (const char*)(x + (size_t)(m0 + r) * E_ + k0 + sg * 4));
            } else if (i < 1536) {
                int t = i - 512, arr = t >> 8, u = t & 255;
                int r = u >> 2, sg = u & 3;
                const uint32_t* src =
                    (arr == 0 ? g_wqh : arr == 1 ? g_wql : arr == 2 ? g_wkh : g_wkl)
                    + r * 512 + ch * 16 + sg * 4;
                uint32_t off = (arr == 0 ? OWH0 : arr == 1 ? OWL0 : arr == 2 ? OWH1 : OWL1);
                CP16(s0 + off + (uint32_t)(r * WSTR + sg * 4) * 4, (const char*)src);
            } else {
                int t = i - 1536, r = t >> 3, sg = t & 7;
                CP16(s0 + OWV + (uint32_t)(r * VSTR + sg * 4) * 4,
                     (const char*)(g_wv + r * 1024 + k0 + sg * 4));
            }
        }
        CP_COMMIT();
    };

    float acc[2][8][4];
#pragma unroll
    for (int s = 0; s < 2; s++)
#pragma unroll
        for (int nt = 0; nt < 8; nt++)
#pragma unroll
            for (int i = 0; i < 4; i++) acc[s][nt][i] = 0.f;

    issue(0, 0);

    for (int ch = 0; ch < 32; ch++) {
        const int st = ch & 1;
        if (ch + 1 < 32) { issue(ch + 1, st ^ 1); CP_WAIT1(); } else { CP_WAIT0(); }
        __syncthreads();

        const char* stage = sm8 + (size_t)st * QSTG;
        const float* Xf = (const float*)(stage + OX);

        if (mat < 2) {
            const uint32_t KWH = sb + (uint32_t)st * QSTG + (mat ? OWH1 : OWH0);
            const uint32_t KWL = sb + (uint32_t)st * QSTG + (mat ? OWL1 : OWL0);
            uint32_t ah[2][2][4], al[2][2][4];
#pragma unroll
            for (int s = 0; s < 2; s++) {
                const int rA = rb0 + s * 16 + g;
#pragma unroll
                for (int kt = 0; kt < 2; kt++) {
                    const int cb = kt * 16 + 2 * c;
                    float2 f00 = *(const float2*)&Xf[rA * XSTR + cb];
                    float2 f10 = *(const float2*)&Xf[(rA + 8) * XSTR + cb];
                    float2 f01 = *(const float2*)&Xf[rA * XSTR + cb + 8];
                    float2 f11 = *(const float2*)&Xf[(rA + 8) * XSTR + cb + 8];
                    bsplit2(f00, ah[s][kt][0], al[s][kt][0]);
                    bsplit2(f10, ah[s][kt][1], al[s][kt][1]);
                    bsplit2(f01, ah[s][kt][2], al[s][kt][2]);
                    bsplit2(f11, ah[s][kt][3], al[s][kt][3]);
                }
            }
#pragma unroll
            for (int nt = 0; nt < 8; nt++) {
                uint32_t bh[4], bl[4];
                ldm4(bh[0], bh[1], bh[2], bh[3], KWH + (uint32_t)nt * 640 + loffw);
                ldm4(bl[0], bl[1], bl[2], bl[3], KWL + (uint32_t)nt * 640 + loffw);
#pragma unroll
                for (int s = 0; s < 2; s++) {
#pragma unroll
                    for (int kt = 0; kt < 2; kt++)
                        mma16b(acc[s][nt], ah[s][kt][0], ah[s][kt][1],
                               ah[s][kt][2], ah[s][kt][3], bh[2 * kt], bh[2 * kt + 1]);
#pragma unroll
                    for (int kt = 0; kt < 2; kt++)
                        mma16b(acc[s][nt], al[s][kt][0], al[s][kt][1],
                               al[s][kt][2], al[s][kt][3], bh[2 * kt], bh[2 * kt + 1]);
#pragma unroll
                    for (int kt = 0; kt < 2; kt++)
                        mma16b(acc[s][nt], ah[s][kt][0], ah[s][kt][1],
                               ah[s][kt][2], ah[s][kt][3], bl[2 * kt], bl[2 * kt + 1]);
                }
            }
        } else {
            const float* WV = (const float*)(stage + OWV);
#pragma unroll
            for (int kt = 0; kt < 4; kt++) {
                const int ka = kt * 8 + c;
                uint32_t aa[2][4];
#pragma unroll
                for (int s = 0; s < 2; s++) {
                    const int rA = rb0 + s * 16 + g;
                    aa[s][0] = fu(tf32r(Xf[rA * XSTR + ka]));
                    aa[s][1] = fu(tf32r(Xf[(rA + 8) * XSTR + ka]));
                    aa[s][2] = fu(tf32r(Xf[rA * XSTR + ka + 4]));
                    aa[s][3] = fu(tf32r(Xf[(rA + 8) * XSTR + ka + 4]));
                }
#pragma unroll
                for (int nt = 0; nt < 8; nt++) {
                    const int br = (nt * 8 + g) * VSTR + ka;
                    const uint32_t b0 = fu(WV[br]), b1 = fu(WV[br + 4]);
#pragma unroll
                    for (int s = 0; s < 2; s++)
                        mma8(acc[s][nt], aa[s][0], aa[s][1], aa[s][2], aa[s][3], b0, b1);
                }
            }
        }
        __syncthreads();
    }

    // ---- epilogue
    if (mat < 2) {
        uint32_t* dh = mat ? g_kbh : g_qbh;
        uint32_t* dl = mat ? g_kbl : g_qbl;
#pragma unroll
        for (int s = 0; s < 2; s++) {
            const int r0 = m0 + rb0 + s * 16 + g, r1 = r0 + 8;
#pragma unroll
            for (int nt = 0; nt < 8; nt++) {
                const int w = nt * 4 + c;
                uint32_t h, l;
                bsplit2(make_float2(acc[s][nt][0], acc[s][nt][1]), h, l);
                dh[(size_t)r0 * 32 + w] = h; dl[(size_t)r0 * 32 + w] = l;
                bsplit2(make_float2(acc[s][nt][2], acc[s][nt][3]), h, l);
                dh[(size_t)r1 * 32 + w] = h; dl[(size_t)r1 * 32 + w] = l;
            }
        }
    } else {
        float* vbuf = (float*)sm8;   // [64][68] in stage0 (stage1 was last read)
#pragma unroll
        for (int s = 0; s < 2; s++) {
            const int rA = rb0 + s * 16 + g;
#pragma unroll
            for (int nt = 0; nt < 8; nt++) {
                vbuf[rA * 68 + nt * 8 + 2 * c]     = acc[s][nt][0];
                vbuf[rA * 68 + nt * 8 + 2 * c + 1] = acc[s][nt][1];
                vbuf[(rA + 8) * 68 + nt * 8 + 2 * c]     = acc[s][nt][2];
                vbuf[(rA + 8) * 68 + nt * 8 + 2 * c + 1] = acc[s][nt][3];
            }
        }
    }
    __syncthreads();
    {
        const float* vbuf = (const float*)sm8;
        const int bb = m0 >> 11;
        const int kw0 = (m0 & 2047) >> 1;
        for (int i = tid; i < 2048; i += 192) {
            int h = i >> 5, w = i & 31;
            float lo = vbuf[(2 * w) * 68 + h];
            float hi = vbuf[(2 * w + 1) * 68 + h];
            g_vt[(size_t)(bb * 64 + h) * 1024 + kw0 + w] = f16x2(hi, lo);
        }
    }
}

// ===========================================================================
// Kernel 2: flash attention, SPLIT-KV, ldmatrix A+B frags.
// __launch_bounds__(128, 3): Q frags reloaded per-iteration via ldmatrix
// (short register lifetime -> no spills at the 170-reg cap), occ 3 -> 1.44
// waves over the 640 active units.
// ===========================================================================
constexpr uint32_t OQBH = 0;
constexpr uint32_t OQBL = 9216;
constexpr uint32_t OKBH = 18432;   // + st*9216
constexpr uint32_t OKBL = 36864;   // + st*9216
constexpr uint32_t OV   = 55296;   // + st*9216
constexpr uint32_t ATT_SMEM = 73728;

__global__ __launch_bounds__(128, 3) void attn_main_kernel(
    float* __restrict__ out, const int* __restrict__ maskp)
{
    const int mask = *maskp;
    const uint32_t u = blockIdx.x;
    const int b  = u >> 7;
    const int jq = (u & 127) >> 2;
    const int cc = u & 3;
    if (mask && 8 * cc > jq) return;

    extern __shared__ char sma[];
    const uint32_t sb = smem_u32(sma);
    const int tid  = threadIdx.x;
    const int warp = tid >> 5, lane = tid & 31;
    const int g = lane >> 2, c = lane & 3;
    const int wb = warp * 16;
    // B-frag ldmatrix lane offset (bytes): row = lane&7 (stride 36 words)
    const uint32_t loffa = (uint32_t)(((lane & 7) * 36 + (lane >> 3) * 4) * 4);
    // A-frag ldmatrix lane offset (words): tiles (r0-7,k0-7)(r8-15,k0-7)
    // (r0-7,k8-15)(r8-15,k8-15) -> rows wb+(lane&7)+((lane>>3)&1)*8,
    // +4 words for lanes>=16.
    const uint32_t qoff = (uint32_t)(((wb + (lane & 7) + ((lane >> 3) & 1) * 8) * 36
                                      + (lane >> 4) * 4) * 4);

    const int t0 = jq * 64;
    const int j0 = 8 * cc;
    const int j1 = mask ? min(8 * cc + 7, jq) : 8 * cc + 7;
    const size_t roff = (size_t)b * T_;

    auto issue_kv = [&](int j, int st) {
        const int s0r = j * 64;
        const uint32_t kb = sb + OKBH + (uint32_t)st * 9216;
        const uint32_t kl = sb + OKBL + (uint32_t)st * 9216;
        const uint32_t vv = sb + OV   + (uint32_t)st * 9216;
        for (int i = tid; i < 1536; i += 128) {
            if (i < 512) {
                int r = i >> 3, sg = i & 7;
                CP16(kb + (uint32_t)(r * 36 + sg * 4) * 4,
                     (const char*)(g_kbh + (roff + s0r + r) * 32 + sg * 4));
            } else if (i < 1024) {
                int t = i - 512, r = t >> 3, sg = t & 7;
                CP16(kl + (uint32_t)(r * 36 + sg * 4) * 4,
                     (const char*)(g_kbl + (roff + s0r + r) * 32 + sg * 4));
            } else {
                int t = i - 1024, h = t >> 3, sg = t & 7;
                CP16(vv + (uint32_t)(h * 36 + sg * 4) * 4,
                     (const char*)(g_vt + (size_t)(b * 64 + h) * 1024
                                   + (s0r >> 1) + sg * 4));
            }
        }
        CP_COMMIT();
    };

    for (int i = tid; i < 1024; i += 128) {
        int arr = i >> 9, t = i & 511, r = t >> 3, sg = t & 7;
        const uint32_t* src = (arr ? g_qbl : g_qbh) + (roff + t0 + r) * 32 + sg * 4;
        CP16(sb + (arr ? OQBL : OQBH) + (uint32_t)(r * 36 + sg * 4) * 4,
             (const char*)src);
    }
    issue_kv(j0, 0);

    CP_WAIT0();
    __syncthreads();

    const float RS = 8.0f * 1.4426950408889634f;   // log2 domain

    float rm[2] = {-CUDART_INF_F, -CUDART_INF_F};
    float rl[2] = {0.f, 0.f};
    float o[8][4];
#pragma unroll
    for (int nt = 0; nt < 8; nt++)
#pragma unroll
        for (int i = 0; i < 4; i++) o[nt][i] = 0.f;

    for (int j = j0; j <= j1; j++) {
        const int st = (j - j0) & 1;
        if (j + 1 <= j1) { issue_kv(j + 1, st ^ 1); CP_WAIT1(); } else { CP_WAIT0(); }
        __syncthreads();

        const uint32_t KBH = sb + OKBH + (uint32_t)st * 9216;
        const uint32_t KBL = sb + OKBL + (uint32_t)st * 9216;
        const uint32_t VB  = sb + OV   + (uint32_t)st * 9216;
        const int s0 = j * 64;

        // ---- load Q fragments for this iteration (short register lifetime)
        uint32_t qh[4][4], ql[4][4];
#pragma unroll
        for (int kt = 0; kt < 4; kt++) {
            ldm4(qh[kt][0], qh[kt][1], qh[kt][2], qh[kt][3],
                 sb + OQBH + qoff + (uint32_t)kt * 32);
            ldm4(ql[kt][0], ql[kt][1], ql[kt][2], ql[kt][3],
                 sb + OQBL + qoff + (uint32_t)kt * 32);
        }

        float sacc[8][4];
#pragma unroll
        for (int nt = 0; nt < 8; nt++)
#pragma unroll
            for (int i = 0; i < 4; i++) sacc[nt][i] = 0.f;

#pragma unroll
        for (int nt = 0; nt < 8; nt++) {
            uint32_t bh[8], bl[8];
            ldm4(bh[0], bh[1], bh[2], bh[3], KBH + (uint32_t)nt * 1152 + loffa);
            ldm4(bh[4], bh[5], bh[6], bh[7], KBH + (uint32_t)nt * 1152 + loffa + 64);
            ldm4(bl[0], bl[1], bl[2], bl[3], KBL + (uint32_t)nt * 1152 + loffa);
            ldm4(bl[4], bl[5], bl[6], bl[7], KBL + (uint32_t)nt * 1152 + loffa + 64);
#pragma unroll
            for (int kt = 0; kt < 4; kt++)
                mma16b(sacc[nt], qh[kt][0], qh[kt][1], qh[kt][2], qh[kt][3],
                       bh[2 * kt], bh[2 * kt + 1]);
#pragma unroll
            for (int kt = 0; kt < 4; kt++)
                mma16b(sacc[nt], ql[kt][0], ql[kt][1], ql[kt][2], ql[kt][3],
                       bh[2 * kt], bh[2 * kt + 1]);
#pragma unroll
            for (int kt = 0; kt < 4; kt++)
                mma16b(sacc[nt], qh[kt][0], qh[kt][1], qh[kt][2], qh[kt][3],
                       bl[2 * kt], bl[2 * kt + 1]);
        }

        const bool diag = (mask != 0) && (j == jq);
#pragma unroll
        for (int nt = 0; nt < 8; nt++) {
#pragma unroll
            for (int e = 0; e < 4; e++) {
                const int sg = s0 + nt * 8 + 2 * c + (e & 1);
                const int tg = t0 + wb + g + (e >> 1) * 8;
                float v = sacc[nt][e] * RS;
                if (diag && sg > tg) v = -CUDART_INF_F;
                sacc[nt][e] = v;
            }
        }

        float alpha[2];
#pragma unroll
        for (int i = 0; i < 2; i++) {
            float m = -CUDART_INF_F;
#pragma unroll
            for (int nt = 0; nt < 8; nt++)
                m = fmaxf(m, fmaxf(sacc[nt][2 * i], sacc[nt][2 * i + 1]));
            m = fmaxf(m, __shfl_xor_sync(0xffffffffu, m, 1));
            m = fmaxf(m, __shfl_xor_sync(0xffffffffu, m, 2));
            const float mnew = fmaxf(rm[i], m);
            alpha[i] = ex2f(rm[i] - mnew);
            float s = 0.f;
#pragma unroll
            for (int nt = 0; nt < 8; nt++) {
                float p0 = ex2f(sacc[nt][2 * i]     - mnew);
                float p1 = ex2f(sacc[nt][2 * i + 1] - mnew);
                sacc[nt][2 * i] = p0; sacc[nt][2 * i + 1] = p1;
                s += p0 + p1;
            }
            s += __shfl_xor_sync(0xffffffffu, s, 1);
            s += __shfl_xor_sync(0xffffffffu, s, 2);
            rl[i] = rl[i] * alpha[i] + s;
            rm[i] = mnew;
        }

        uint32_t aa[4][4];
#pragma unroll
        for (int kt = 0; kt < 4; kt++) {
            aa[kt][0] = f16x2(sacc[2 * kt][1],     sacc[2 * kt][0]);
            aa[kt][1] = f16x2(sacc[2 * kt][3],     sacc[2 * kt][2]);
            aa[kt][2] = f16x2(sacc[2 * kt + 1][1], sacc[2 * kt + 1][0]);
            aa[kt][3] = f16x2(sacc[2 * kt + 1][3], sacc[2 * kt + 1][2]);
        }
#pragma unroll
        for (int nt = 0; nt < 8; nt++) {
            o[nt][0] *= alpha[0]; o[nt][1] *= alpha[0];
            o[nt][2] *= alpha[1]; o[nt][3] *= alpha[1];
        }
#pragma unroll
        for (int nt = 0; nt < 8; nt++) {
            uint32_t vt[8];
            ldm4(vt[0], vt[1], vt[2], vt[3], VB + (uint32_t)nt * 1152 + loffa);
            ldm4(vt[4], vt[5], vt[6], vt[7], VB + (uint32_t)nt * 1152 + loffa + 64);
#pragma unroll
            for (int kt = 0; kt < 4; kt++)
                mma16f(o[nt], aa[kt][0], aa[kt][1], aa[kt][2], aa[kt][3],
                       vt[2 * kt], vt[2 * kt + 1]);
        }
        __syncthreads();
    }

    if (mask && jq < 8) {
        const float inv0 = 1.0f / rl[0], inv1 = 1.0f / rl[1];
        const size_t r0o = roff + t0 + wb + g;
#pragma unroll
        for (int nt = 0; nt < 8; nt++) {
            *(float2*)&out[r0o * H_ + nt * 8 + 2 * c] =
                make_float2(o[nt][0] * inv0, o[nt][1] * inv0);
            *(float2*)&out[(r0o + 8) * H_ + nt * 8 + 2 * c] =
                make_float2(o[nt][2] * inv1, o[nt][3] * inv1);
        }
        return;
    }

    float* po = g_po + (size_t)u * 4096;
    const int r0 = wb + g;
#pragma unroll
    for (int nt = 0; nt < 8; nt++) {
        *(float2*)&po[r0 * 64 + nt * 8 + 2 * c] = make_float2(o[nt][0], o[nt][1]);
        *(float2*)&po[(r0 + 8) * 64 + nt * 8 + 2 * c] = make_float2(o[nt][2], o[nt][3]);
    }
    if (c == 0) {
        g_pm[u * 64 + r0] = rm[0];     g_pl[u * 64 + r0] = rl[0];
        g_pm[u * 64 + r0 + 8] = rm[1]; g_pl[u * 64 + r0 + 8] = rl[1];
    }
}

// ===========================================================================
// Kernel 3: split-KV combine. 512 CTAs (b, jq, row-half), 128 threads.
// (round-12 measured-best configuration)
// ===========================================================================
__global__ __launch_bounds__(128) void combine_kernel(
    float* __restrict__ out, const int* __restrict__ maskp)
{
    const int bid = blockIdx.x;
    const int half = bid & 1;
    const int blk = bid >> 1;          // 0..255
    const int b = blk >> 5, jq = blk & 31;
    const int mask = *maskp;
    if (mask && jq < 8) return;        // written directly by attn_main
    const int nc = mask ? (jq >> 3) + 1 : 4;
    const int t = threadIdx.x;
    const int r = half * 32 + (t >> 2);   // row 0..63
    const int q = (t & 3) * 16;           // col base
    const uint32_t ub = (uint32_t)((b << 7) | (jq << 2));

    float m[4], l[4];
    float M = -CUDART_INF_F;
#pragma unroll 4
    for (int i = 0; i < nc; i++) {
        m[i] = g_pm[(ub + i) * 64 + r];
        l[i] = g_pl[(ub + i) * 64 + r];
        M = fmaxf(M, m[i]);
    }
    float L = 0.f, w[4];
#pragma unroll 4
    for (int i = 0; i < nc; i++) {
        w[i] = ex2f(m[i] - M);
        L += l[i] * w[i];
    }

    float4 acc[4];
#pragma unroll
    for (int k = 0; k < 4; k++) acc[k] = make_float4(0.f, 0.f, 0.f, 0.f);
#pragma unroll 4
    for (int i = 0; i < nc; i++) {
        const float* src = g_po + (size_t)(ub + i) * 4096 + r * 64 + q;
        const float wi = w[i];
#pragma unroll
        for (int k = 0; k < 4; k++) {
            float4 v = *(const float4*)&src[k * 4];
            acc[k].x += wi * v.x; acc[k].y += wi * v.y;
            acc[k].z += wi * v.z; acc[k].w += wi * v.w;
        }
    }
    const float inv = 1.0f / L;
    float* dst = out + ((size_t)b * T_ + jq * 64 + r) * H_ + q;
#pragma unroll
    for (int k = 0; k < 4; k++) {
        float4 v = make_float4(acc[k].x * inv, acc[k].y * inv,
                               acc[k].z * inv, acc[k].w * inv);
        *(float4*)&dst[k * 4] = v;
    }
}

// ---------------------------------------------------------------------------
extern "C" void kernel_launch(void* const* d_in, const int* in_sizes, int n_in,
                              void* d_out, int out_size)
{
    const float* x  = (const float*)d_in[0];
    const float* Wq = (const float*)d_in[1];
    const float* Wk = (const float*)d_in[2];
    const float* Wv = (const float*)d_in[3];
    const int* should_mask = (const int*)d_in[4];
    float* out = (float*)d_out;

    cudaFuncSetAttribute(qkv_kernel,
                         cudaFuncAttributeMaxDynamicSharedMemorySize, QKV_SMEM);
    cudaFuncSetAttribute(attn_main_kernel,
                         cudaFuncAttributeMaxDynamicSharedMemorySize, ATT_SMEM);

    prep_kernel<<<dim3(64, 3), 256>>>(Wq, Wk, Wv);
    qkv_kernel<<<256, 192, QKV_SMEM>>>(x);
    attn_main_kernel<<<1024, 128, ATT_SMEM>>>(out, should_mask);
    combine_kernel<<<512, 128>>>(out, should_mask);
}

// round 16
// speedup vs baseline: 1.0596x; 1.0596x over previous
#include <cuda_runtime.h>
#include <math.h>
#include <math_constants.h>
#include <cstdint>

// Problem shape (fixed by the reference)
constexpr int B_ = 8;
constexpr int T_ = 2048;
constexpr int E_ = 1024;
constexpr int H_ = 64;
constexpr int MT = B_ * T_;   // 16384 rows

// ---------------------------------------------------------------------------
// Device globals (no allocs allowed)
// ---------------------------------------------------------------------------
__device__ __align__(16) uint32_t g_wqh[64 * 512];
__device__ __align__(16) uint32_t g_wql[64 * 512];
__device__ __align__(16) uint32_t g_wkh[64 * 512];
__device__ __align__(16) uint32_t g_wkl[64 * 512];
__device__ __align__(16) float    g_wv [64 * 1024];   // tf32-rounded

__device__ __align__(16) uint32_t g_qbh[MT * 32];
__device__ __align__(16) uint32_t g_qbl[MT * 32];
__device__ __align__(16) uint32_t g_kbh[MT * 32];
__device__ __align__(16) uint32_t g_kbl[MT * 32];
// V^T, fp16 packed along keys: g_vt[(b*64 + h)*1024 + w] = v[b][2w..2w+1][h]
__device__ __align__(16) uint32_t g_vt [B_ * 64 * 1024];

// Split-KV scratch: 1024 units (b 0..7, jq 0..31, chunk 0..3)
__device__ __align__(16) float g_po[1024 * 4096];
__device__ float g_pm[1024 * 64];
__device__ float g_pl[1024 * 64];

// ===========================================================================
// Baseline-PTX helpers (all valid at compute_103)
// ===========================================================================
__device__ __forceinline__ uint32_t smem_u32(const void* p) {
    uint32_t a;
    asm("{ .reg .u64 t; cvta.to.shared.u64 t, %1; cvt.u32.u64 %0, t; }"
        : "=r"(a) : "l"(p));
    return a;
}
__device__ __forceinline__ float tf32r(float v) {
    uint32_t u;
    asm("cvt.rna.tf32.f32 %0, %1;" : "=r"(u) : "f"(v));
    return __uint_as_float(u);
}
__device__ __forceinline__ float ex2f(float x) {
    float r;
    asm("ex2.approx.f32 %0, %1;" : "=f"(r) : "f"(x));
    return r;
}
// Pack float2 -> bf16x2 hi word + bf16x2 lo word (hi = rn(v), lo = rn(v-hi))
__device__ __forceinline__ void bsplit2(float2 f, uint32_t& h, uint32_t& l) {
    asm("cvt.rn.bf16x2.f32 %0, %1, %2;" : "=r"(h) : "f"(f.y), "f"(f.x));
    float hx = __uint_as_float(h << 16);
    float hy = __uint_as_float(h & 0xffff0000u);
    asm("cvt.rn.bf16x2.f32 %0, %1, %2;" : "=r"(l) : "f"(f.y - hy), "f"(f.x - hx));
}
// Pack (hi, lo) floats -> fp16x2 word (low half = lo)
__device__ __forceinline__ uint32_t f16x2(float hi, float lo) {
    uint32_t r;
    asm("cvt.rn.f16x2.f32 %0, %1, %2;" : "=r"(r) : "f"(hi), "f"(lo));
    return r;
}
// ldmatrix: 4x (8x8 b16) tiles, no transpose
__device__ __forceinline__ void ldm4(uint32_t& r0, uint32_t& r1,
                                     uint32_t& r2, uint32_t& r3, uint32_t addr) {
    asm volatile("ldmatrix.sync.aligned.m8n8.x4.shared.b16 {%0,%1,%2,%3}, [%4];"
        : "=r"(r0), "=r"(r1), "=r"(r2), "=r"(r3) : "r"(addr));
}
// D += A(16x16) * B(16x8), bf16 inputs, fp32 accum
__device__ __forceinline__ void mma16b(float* c,
                                       uint32_t a0, uint32_t a1, uint32_t a2, uint32_t a3,
                                       uint32_t b0, uint32_t b1) {
    asm volatile(
        "mma.sync.aligned.m16n8k16.row.col.f32.bf16.bf16.f32 "
        "{%0,%1,%2,%3}, {%4,%5,%6,%7}, {%8,%9}, {%0,%1,%2,%3};"
        : "+f"(c[0]), "+f"(c[1]), "+f"(c[2]), "+f"(c[3])
        : "r"(a0), "r"(a1), "r"(a2), "r"(a3), "r"(b0), "r"(b1));
}
// D += A(16x16) * B(16x8), fp16 inputs, fp32 accum
__device__ __forceinline__ void mma16f(float* c,
                                       uint32_t a0, uint32_t a1, uint32_t a2, uint32_t a3,
                                       uint32_t b0, uint32_t b1) {
    asm volatile(
        "mma.sync.aligned.m16n8k16.row.col.f32.f16.f16.f32 "
        "{%0,%1,%2,%3}, {%4,%5,%6,%7}, {%8,%9}, {%0,%1,%2,%3};"
        : "+f"(c[0]), "+f"(c[1]), "+f"(c[2]), "+f"(c[3])
        : "r"(a0), "r"(a1), "r"(a2), "r"(a3), "r"(b0), "r"(b1));
}
// D += A(16x8) * B(8x8), tf32 inputs, fp32 accum
__device__ __forceinline__ void mma8(float* c,
                                     uint32_t a0, uint32_t a1, uint32_t a2, uint32_t a3,
                                     uint32_t b0, uint32_t b1) {
    asm volatile(
        "mma.sync.aligned.m16n8k8.row.col.f32.tf32.tf32.f32 "
        "{%0,%1,%2,%3}, {%4,%5,%6,%7}, {%8,%9}, {%0,%1,%2,%3};"
        : "+f"(c[0]), "+f"(c[1]), "+f"(c[2]), "+f"(c[3])
        : "r"(a0), "r"(a1), "r"(a2), "r"(a3), "r"(b0), "r"(b1));
}
__device__ __forceinline__ uint32_t fu(float v) { return __float_as_uint(v); }

#define CP16(d, s)  asm volatile("cp.async.ca.shared.global [%0], [%1], 16;" :: "r"(d), "l"(s))
#define CP_COMMIT() asm volatile("cp.async.commit_group;" ::: "memory")
#define CP_WAIT0()  asm volatile("cp.async.wait_group 0;" ::: "memory")
#define CP_WAIT1()  asm volatile("cp.async.wait_group 1;" ::: "memory")

// ===========================================================================
// Kernel 0: weight prep. Wq/Wk -> packed bf16 hi/lo; Wv -> tf32-rounded.
// ===========================================================================
__global__ void prep_kernel(const float* __restrict__ Wq,
                            const float* __restrict__ Wk,
                            const float* __restrict__ Wv)
{
    const int r = blockIdx.x, mat = blockIdx.y, tid = threadIdx.x;
    if (mat < 2) {
        const float* W = mat ? Wk : Wq;
        uint32_t* dh = mat ? g_wkh : g_wqh;
        uint32_t* dl = mat ? g_wkl : g_wql;
        if (tid < 256) {
            float4 f = *reinterpret_cast<const float4*>(&W[r * 1024 + 4 * tid]);
            uint32_t h0, l0, h1, l1;
            bsplit2(make_float2(f.x, f.y), h0, l0);
            bsplit2(make_float2(f.z, f.w), h1, l1);
            *reinterpret_cast<uint2*>(&dh[r * 512 + 2 * tid]) = make_uint2(h0, h1);
            *reinterpret_cast<uint2*>(&dl[r * 512 + 2 * tid]) = make_uint2(l0, l1);
        }
    } else {
        float4 f = *reinterpret_cast<const float4*>(&Wv[r * 1024 + 4 * tid]);
        float4 o = make_float4(tf32r(f.x), tf32r(f.y), tf32r(f.z), tf32r(f.w));
        *reinterpret_cast<float4*>(&g_wv[r * 1024 + 4 * tid]) = o;
    }
}

// ===========================================================================
// Kernel 1: merged QKV projection — 128 rows/CTA, grid 128, 384 threads
// (12 warps: 4Q/4K/4V; warp = 32 rows as two 16-row MMA sets).
// Halves per-CTA-amortized W L2 traffic vs the 64-row tiling.
// ===========================================================================
constexpr int XSTR = 40;
constexpr int WSTR = 20;
constexpr int VSTR = 36;
constexpr uint32_t OX   = 0;                       // x: 128 x 40 f32 = 20480 B
constexpr uint32_t OWH0 = 20480;                   // each W chunk: 64 x 20 u32 = 5120 B
constexpr uint32_t OWL0 = 25600;
constexpr uint32_t OWH1 = 30720;
constexpr uint32_t OWL1 = 35840;
constexpr uint32_t OWV  = 40960;                   // wv: 64 x 36 f32 = 9216 B
constexpr uint32_t QSTG = 50176;
constexpr uint32_t QKV_SMEM = 2 * QSTG;            // 100352 bytes

__global__ __launch_bounds__(384, 1) void qkv_kernel(const float* __restrict__ x)
{
    extern __shared__ char sm8[];
    const uint32_t sb = smem_u32(sm8);
    const int tid  = threadIdx.x;
    const int wid  = tid >> 5, lane = tid & 31;
    const int g = lane >> 2, c = lane & 3;
    const int mat = wid >> 2;          // 0=Q, 1=K, 2=V
    const int rb0 = (wid & 3) * 32;    // warp row base (2 sets of 16)
    const int m0  = blockIdx.x * 128;
    const uint32_t loffw = (uint32_t)(((lane & 7) * WSTR + (lane >> 3) * 4) * 4);

    auto issue = [&](int ch, int st) {
        const uint32_t s0 = sb + (uint32_t)st * QSTG;
        const int k0 = ch * 32;
        for (int i = tid; i < 2560; i += 384) {
            if (i < 1024) {
                int r = i >> 3, sg = i & 7;
                CP16(s0 + OX + (uint32_t)(r * XSTR + sg * 4) * 4,
                     (const char*)(x + (size_t)(m0 + r) * E_ + k0 + sg * 4));
            } else if (i < 2048) {
                int t = i - 1024, arr = t >> 8, u = t & 255;
                int r = u >> 2, sg = u & 3;
                const uint32_t* src =
                    (arr == 0 ? g_wqh : arr == 1 ? g_wql : arr == 2 ? g_wkh : g_wkl)
                    + r * 512 + ch * 16 + sg * 4;
                uint32_t off = (arr == 0 ? OWH0 : arr == 1 ? OWL0 : arr == 2 ? OWH1 : OWL1);
                CP16(s0 + off + (uint32_t)(r * WSTR + sg * 4) * 4, (const char*)src);
            } else {
                int t = i - 2048, r = t >> 3, sg = t & 7;
                CP16(s0 + OWV + (uint32_t)(r * VSTR + sg * 4) * 4,
                     (const char*)(g_wv + r * 1024 + k0 + sg * 4));
            }
        }
        CP_COMMIT();
    };

    float acc[2][8][4];
#pragma unroll
    for (int s = 0; s < 2; s++)
#pragma unroll
        for (int nt = 0; nt < 8; nt++)
#pragma unroll
            for (int i = 0; i < 4; i++) acc[s][nt][i] = 0.f;

    issue(0, 0);

    for (int ch = 0; ch < 32; ch++) {
        const int st = ch & 1;
        if (ch + 1 < 32) { issue(ch + 1, st ^ 1); CP_WAIT1(); } else { CP_WAIT0(); }
        __syncthreads();

        const char* stage = sm8 + (size_t)st * QSTG;
        const float* Xf = (const float*)(stage + OX);

        if (mat < 2) {
            const uint32_t KWH = sb + (uint32_t)st * QSTG + (mat ? OWH1 : OWH0);
            const uint32_t KWL = sb + (uint32_t)st * QSTG + (mat ? OWL1 : OWL0);
            uint32_t ah[2][2][4], al[2][2][4];
#pragma unroll
            for (int s = 0; s < 2; s++) {
                const int rA = rb0 + s * 16 + g;
#pragma unroll
                for (int kt = 0; kt < 2; kt++) {
                    const int cb = kt * 16 + 2 * c;
                    float2 f00 = *(const float2*)&Xf[rA * XSTR + cb];
                    float2 f10 = *(const float2*)&Xf[(rA + 8) * XSTR + cb];
                    float2 f01 = *(const float2*)&Xf[rA * XSTR + cb + 8];
                    float2 f11 = *(const float2*)&Xf[(rA + 8) * XSTR + cb + 8];
                    bsplit2(f00, ah[s][kt][0], al[s][kt][0]);
                    bsplit2(f10, ah[s][kt][1], al[s][kt][1]);
                    bsplit2(f01, ah[s][kt][2], al[s][kt][2]);
                    bsplit2(f11, ah[s][kt][3], al[s][kt][3]);
                }
            }
#pragma unroll
            for (int nt = 0; nt < 8; nt++) {
                uint32_t bh[4], bl[4];
                ldm4(bh[0], bh[1], bh[2], bh[3], KWH + (uint32_t)nt * 640 + loffw);
                ldm4(bl[0], bl[1], bl[2], bl[3], KWL + (uint32_t)nt * 640 + loffw);
#pragma unroll
                for (int s = 0; s < 2; s++) {
#pragma unroll
                    for (int kt = 0; kt < 2; kt++)
                        mma16b(acc[s][nt], ah[s][kt][0], ah[s][kt][1],
                               ah[s][kt][2], ah[s][kt][3], bh[2 * kt], bh[2 * kt + 1]);
#pragma unroll
                    for (int kt = 0; kt < 2; kt++)
                        mma16b(acc[s][nt], al[s][kt][0], al[s][kt][1],
                               al[s][kt][2], al[s][kt][3], bh[2 * kt], bh[2 * kt + 1]);
#pragma unroll
                    for (int kt = 0; kt < 2; kt++)
                        mma16b(acc[s][nt], ah[s][kt][0], ah[s][kt][1],
                               ah[s][kt][2], ah[s][kt][3], bl[2 * kt], bl[2 * kt + 1]);
                }
            }
        } else {
            const float* WV = (const float*)(stage + OWV);
#pragma unroll
            for (int kt = 0; kt < 4; kt++) {
                const int ka = kt * 8 + c;
                uint32_t aa[2][4];
#pragma unroll
                for (int s = 0; s < 2; s++) {
                    const int rA = rb0 + s * 16 + g;
                    aa[s][0] = fu(tf32r(Xf[rA * XSTR + ka]));
                    aa[s][1] = fu(tf32r(Xf[(rA + 8) * XSTR + ka]));
                    aa[s][2] = fu(tf32r(Xf[rA * XSTR + ka + 4]));
                    aa[s][3] = fu(tf32r(Xf[(rA + 8) * XSTR + ka + 4]));
                }
#pragma unroll
                for (int nt = 0; nt < 8; nt++) {
                    const int br = (nt * 8 + g) * VSTR + ka;
                    const uint32_t b0 = fu(WV[br]), b1 = fu(WV[br + 4]);
#pragma unroll
                    for (int s = 0; s < 2; s++)
                        mma8(acc[s][nt], aa[s][0], aa[s][1], aa[s][2], aa[s][3], b0, b1);
                }
            }
        }
        __syncthreads();
    }

    // ---- epilogue
    if (mat < 2) {
        uint32_t* dh = mat ? g_kbh : g_qbh;
        uint32_t* dl = mat ? g_kbl : g_qbl;
#pragma unroll
        for (int s = 0; s < 2; s++) {
            const int r0 = m0 + rb0 + s * 16 + g, r1 = r0 + 8;
#pragma unroll
            for (int nt = 0; nt < 8; nt++) {
                const int w = nt * 4 + c;
                uint32_t h, l;
                bsplit2(make_float2(acc[s][nt][0], acc[s][nt][1]), h, l);
                dh[(size_t)r0 * 32 + w] = h; dl[(size_t)r0 * 32 + w] = l;
                bsplit2(make_float2(acc[s][nt][2], acc[s][nt][3]), h, l);
                dh[(size_t)r1 * 32 + w] = h; dl[(size_t)r1 * 32 + w] = l;
            }
        }
    } else {
        float* vbuf = (float*)sm8;   // [128][68] = 34816 B, fits in stage area
#pragma unroll
        for (int s = 0; s < 2; s++) {
            const int rA = rb0 + s * 16 + g;
#pragma unroll
            for (int nt = 0; nt < 8; nt++) {
                vbuf[rA * 68 + nt * 8 + 2 * c]     = acc[s][nt][0];
                vbuf[rA * 68 + nt * 8 + 2 * c + 1] = acc[s][nt][1];
                vbuf[(rA + 8) * 68 + nt * 8 + 2 * c]     = acc[s][nt][2];
                vbuf[(rA + 8) * 68 + nt * 8 + 2 * c + 1] = acc[s][nt][3];
            }
        }
    }
    __syncthreads();
    {
        // transposed packed-fp16 write of the 128-row V tile (64 key-words)
        const float* vbuf = (const float*)sm8;
        const int bb = m0 >> 11;
        const int kw0 = (m0 & 2047) >> 1;
        for (int i = tid; i < 4096; i += 384) {
            int h = i >> 6, w = i & 63;
            float lo = vbuf[(2 * w) * 68 + h];
            float hi = vbuf[(2 * w + 1) * 68 + h];
            g_vt[(size_t)(bb * 64 + h) * 1024 + kw0 + w] = f16x2(hi, lo);
        }
    }
}

// ===========================================================================
// Kernel 2: flash attention, SPLIT-KV (round-14 proven best configuration:
// hoisted Q fragments, __launch_bounds__(128, 2)).
// ===========================================================================
constexpr uint32_t OQBH = 0;
constexpr uint32_t OQBL = 9216;
constexpr uint32_t OKBH = 18432;   // + st*9216
constexpr uint32_t OKBL = 36864;   // + st*9216
constexpr uint32_t OV   = 55296;   // + st*9216
constexpr uint32_t ATT_SMEM = 73728;

__global__ __launch_bounds__(128, 2) void attn_main_kernel(
    float* __restrict__ out, const int* __restrict__ maskp)
{
    const int mask = *maskp;
    const uint32_t u = blockIdx.x;
    const int b  = u >> 7;
    const int jq = (u & 127) >> 2;
    const int cc = u & 3;
    if (mask && 8 * cc > jq) return;

    extern __shared__ char sma[];
    const uint32_t sb = smem_u32(sma);
    const int tid  = threadIdx.x;
    const int warp = tid >> 5, lane = tid & 31;
    const int g = lane >> 2, c = lane & 3;
    const int wb = warp * 16;
    const uint32_t loffa = (uint32_t)(((lane & 7) * 36 + (lane >> 3) * 4) * 4);

    const int t0 = jq * 64;
    const int j0 = 8 * cc;
    const int j1 = mask ? min(8 * cc + 7, jq) : 8 * cc + 7;
    const size_t roff = (size_t)b * T_;

    auto issue_kv = [&](int j, int st) {
        const int s0r = j * 64;
        const uint32_t kb = sb + OKBH + (uint32_t)st * 9216;
        const uint32_t kl = sb + OKBL + (uint32_t)st * 9216;
        const uint32_t vv = sb + OV   + (uint32_t)st * 9216;
        for (int i = tid; i < 1536; i += 128) {
            if (i < 512) {
                int r = i >> 3, sg = i & 7;
                CP16(kb + (uint32_t)(r * 36 + sg * 4) * 4,
                     (const char*)(g_kbh + (roff + s0r + r) * 32 + sg * 4));
            } else if (i < 1024) {
                int t = i - 512, r = t >> 3, sg = t & 7;
                CP16(kl + (uint32_t)(r * 36 + sg * 4) * 4,
                     (const char*)(g_kbl + (roff + s0r + r) * 32 + sg * 4));
            } else {
                int t = i - 1024, h = t >> 3, sg = t & 7;
                CP16(vv + (uint32_t)(h * 36 + sg * 4) * 4,
                     (const char*)(g_vt + (size_t)(b * 64 + h) * 1024
                                   + (s0r >> 1) + sg * 4));
            }
        }
        CP_COMMIT();
    };

    for (int i = tid; i < 1024; i += 128) {
        int arr = i >> 9, t = i & 511, r = t >> 3, sg = t & 7;
        const uint32_t* src = (arr ? g_qbl : g_qbh) + (roff + t0 + r) * 32 + sg * 4;
        CP16(sb + (arr ? OQBL : OQBH) + (uint32_t)(r * 36 + sg * 4) * 4,
             (const char*)src);
    }
    issue_kv(j0, 0);

    const uint32_t* Qbh = (const uint32_t*)(sma + OQBH);
    const uint32_t* Qbl = (const uint32_t*)(sma + OQBL);

    CP_WAIT0();
    __syncthreads();
    uint32_t qh[4][4], ql[4][4];
#pragma unroll
    for (int kt = 0; kt < 4; kt++) {
        const int ra = (wb + g) * 36 + kt * 8 + c;
        const int rb = (wb + g + 8) * 36 + kt * 8 + c;
        qh[kt][0] = Qbh[ra]; qh[kt][1] = Qbh[rb];
        qh[kt][2] = Qbh[ra + 4]; qh[kt][3] = Qbh[rb + 4];
        ql[kt][0] = Qbl[ra]; ql[kt][1] = Qbl[rb];
        ql[kt][2] = Qbl[ra + 4]; ql[kt][3] = Qbl[rb + 4];
    }

    const float RS = 8.0f * 1.4426950408889634f;   // log2 domain

    float rm[2] = {-CUDART_INF_F, -CUDART_INF_F};
    float rl[2] = {0.f, 0.f};
    float o[8][4];
#pragma unroll
    for (int nt = 0; nt < 8; nt++)
#pragma unroll
        for (int i = 0; i < 4; i++) o[nt][i] = 0.f;

    for (int j = j0; j <= j1; j++) {
        const int st = (j - j0) & 1;
        if (j + 1 <= j1) { issue_kv(j + 1, st ^ 1); CP_WAIT1(); } else { CP_WAIT0(); }
        __syncthreads();

        const uint32_t KBH = sb + OKBH + (uint32_t)st * 9216;
        const uint32_t KBL = sb + OKBL + (uint32_t)st * 9216;
        const uint32_t VB  = sb + OV   + (uint32_t)st * 9216;
        const int s0 = j * 64;

        float sacc[8][4];
#pragma unroll
        for (int nt = 0; nt < 8; nt++)
#pragma unroll
            for (int i = 0; i < 4; i++) sacc[nt][i] = 0.f;

#pragma unroll
        for (int nt = 0; nt < 8; nt++) {
            uint32_t bh[8], bl[8];
            ldm4(bh[0], bh[1], bh[2], bh[3], KBH + (uint32_t)nt * 1152 + loffa);
            ldm4(bh[4], bh[5], bh[6], bh[7], KBH + (uint32_t)nt * 1152 + loffa + 64);
            ldm4(bl[0], bl[1], bl[2], bl[3], KBL + (uint32_t)nt * 1152 + loffa);
            ldm4(bl[4], bl[5], bl[6], bl[7], KBL + (uint32_t)nt * 1152 + loffa + 64);
#pragma unroll
            for (int kt = 0; kt < 4; kt++)
                mma16b(sacc[nt], qh[kt][0], qh[kt][1], qh[kt][2], qh[kt][3],
                       bh[2 * kt], bh[2 * kt + 1]);
#pragma unroll
            for (int kt = 0; kt < 4; kt++)
                mma16b(sacc[nt], ql[kt][0], ql[kt][1], ql[kt][2], ql[kt][3],
                       bh[2 * kt], bh[2 * kt + 1]);
#pragma unroll
            for (int kt = 0; kt < 4; kt++)
                mma16b(sacc[nt], qh[kt][0], qh[kt][1], qh[kt][2], qh[kt][3],
                       bl[2 * kt], bl[2 * kt + 1]);
        }

        const bool diag = (mask != 0) && (j == jq);
#pragma unroll
        for (int nt = 0; nt < 8; nt++) {
#pragma unroll
            for (int e = 0; e < 4; e++) {
                const int sg = s0 + nt * 8 + 2 * c + (e & 1);
                const int tg = t0 + wb + g + (e >> 1) * 8;
                float v = sacc[nt][e] * RS;
                if (diag && sg > tg) v = -CUDART_INF_F;
                sacc[nt][e] = v;
            }
        }

        float alpha[2];
#pragma unroll
        for (int i = 0; i < 2; i++) {
            float m = -CUDART_INF_F;
#pragma unroll
            for (int nt = 0; nt < 8; nt++)
                m = fmaxf(m, fmaxf(sacc[nt][2 * i], sacc[nt][2 * i + 1]));
            m = fmaxf(m, __shfl_xor_sync(0xffffffffu, m, 1));
            m = fmaxf(m, __shfl_xor_sync(0xffffffffu, m, 2));
            const float mnew = fmaxf(rm[i], m);
            alpha[i] = ex2f(rm[i] - mnew);
            float s = 0.f;
#pragma unroll
            for (int nt = 0; nt < 8; nt++) {
                float p0 = ex2f(sacc[nt][2 * i]     - mnew);
                float p1 = ex2f(sacc[nt][2 * i + 1] - mnew);
                sacc[nt][2 * i] = p0; sacc[nt][2 * i + 1] = p1;
                s += p0 + p1;
            }
            s += __shfl_xor_sync(0xffffffffu, s, 1);
            s += __shfl_xor_sync(0xffffffffu, s, 2);
            rl[i] = rl[i] * alpha[i] + s;
            rm[i] = mnew;
        }

        uint32_t aa[4][4];
#pragma unroll
        for (int kt = 0; kt < 4; kt++) {
            aa[kt][0] = f16x2(sacc[2 * kt][1],     sacc[2 * kt][0]);
            aa[kt][1] = f16x2(sacc[2 * kt][3],     sacc[2 * kt][2]);
            aa[kt][2] = f16x2(sacc[2 * kt + 1][1], sacc[2 * kt + 1][0]);
            aa[kt][3] = f16x2(sacc[2 * kt + 1][3], sacc[2 * kt + 1][2]);
        }
#pragma unroll
        for (int nt = 0; nt < 8; nt++) {
            o[nt][0] *= alpha[0]; o[nt][1] *= alpha[0];
            o[nt][2] *= alpha[1]; o[nt][3] *= alpha[1];
        }
#pragma unroll
        for (int nt = 0; nt < 8; nt++) {
            uint32_t vt[8];
            ldm4(vt[0], vt[1], vt[2], vt[3], VB + (uint32_t)nt * 1152 + loffa);
            ldm4(vt[4], vt[5], vt[6], vt[7], VB + (uint32_t)nt * 1152 + loffa + 64);
#pragma unroll
            for (int kt = 0; kt < 4; kt++)
                mma16f(o[nt], aa[kt][0], aa[kt][1], aa[kt][2], aa[kt][3],
                       vt[2 * kt], vt[2 * kt + 1]);
        }
        __syncthreads();
    }

    if (mask && jq < 8) {
        const float inv0 = 1.0f / rl[0], inv1 = 1.0f / rl[1];
        const size_t r0o = roff + t0 + wb + g;
#pragma unroll
        for (int nt = 0; nt < 8; nt++) {
            *(float2*)&out[r0o * H_ + nt * 8 + 2 * c] =
                make_float2(o[nt][0] * inv0, o[nt][1] * inv0);
            *(float2*)&out[(r0o + 8) * H_ + nt * 8 + 2 * c] =
                make_float2(o[nt][2] * inv1, o[nt][3] * inv1);
        }
        return;
    }

    float* po = g_po + (size_t)u * 4096;
    const int r0 = wb + g;
#pragma unroll
    for (int nt = 0; nt < 8; nt++) {
        *(float2*)&po[r0 * 64 + nt * 8 + 2 * c] = make_float2(o[nt][0], o[nt][1]);
        *(float2*)&po[(r0 + 8) * 64 + nt * 8 + 2 * c] = make_float2(o[nt][2], o[nt][3]);
    }
    if (c == 0) {
        g_pm[u * 64 + r0] = rm[0];     g_pl[u * 64 + r0] = rl[0];
        g_pm[u * 64 + r0 + 8] = rm[1]; g_pl[u * 64 + r0 + 8] = rl[1];
    }
}

// ===========================================================================
// Kernel 3: split-KV combine. 512 CTAs (b, jq, row-half), 128 threads.
// ===========================================================================
__global__ __launch_bounds__(128) void combine_kernel(
    float* __restrict__ out, const int* __restrict__ maskp)
{
    const int bid = blockIdx.x;
    const int half = bid & 1;
    const int blk = bid >> 1;          // 0..255
    const int b = blk >> 5, jq = blk & 31;
    const int mask = *maskp;
    if (mask && jq < 8) return;        // written directly by attn_main
    const int nc = mask ? (jq >> 3) + 1 : 4;
    const int t = threadIdx.x;
    const int r = half * 32 + (t >> 2);   // row 0..63
    const int q = (t & 3) * 16;           // col base
    const uint32_t ub = (uint32_t)((b << 7) | (jq << 2));

    float m[4], l[4];
    float M = -CUDART_INF_F;
#pragma unroll 4
    for (int i = 0; i < nc; i++) {
        m[i] = g_pm[(ub + i) * 64 + r];
        l[i] = g_pl[(ub + i) * 64 + r];
        M = fmaxf(M, m[i]);
    }
    float L = 0.f, w[4];
#pragma unroll 4
    for (int i = 0; i < nc; i++) {
        w[i] = ex2f(m[i] - M);
        L += l[i] * w[i];
    }

    float4 acc[4];
#pragma unroll
    for (int k = 0; k < 4; k++) acc[k] = make_float4(0.f, 0.f, 0.f, 0.f);
#pragma unroll 4
    for (int i = 0; i < nc; i++) {
        const float* src = g_po + (size_t)(ub + i) * 4096 + r * 64 + q;
        const float wi = w[i];
#pragma unroll
        for (int k = 0; k < 4; k++) {
            float4 v = *(const float4*)&src[k * 4];
            acc[k].x += wi * v.x; acc[k].y += wi * v.y;
            acc[k].z += wi * v.z; acc[k].w += wi * v.w;
        }
    }
    const float inv = 1.0f / L;
    float* dst = out + ((size_t)b * T_ + jq * 64 + r) * H_ + q;
#pragma unroll
    for (int k = 0; k < 4; k++) {
        float4 v = make_float4(acc[k].x * inv, acc[k].y * inv,
                               acc[k].z * inv, acc[k].w * inv);
        *(float4*)&dst[k * 4] = v;
    }
}

// ---------------------------------------------------------------------------
extern "C" void kernel_launch(void* const* d_in, const int* in_sizes, int n_in,
                              void* d_out, int out_size)
{
    const float* x  = (const float*)d_in[0];
    const float* Wq = (const float*)d_in[1];
    const float* Wk = (const float*)d_in[2];
    const float* Wv = (const float*)d_in[3];
    const int* should_mask = (const int*)d_in[4];
    float* out = (float*)d_out;

    cudaFuncSetAttribute(qkv_kernel,
                         cudaFuncAttributeMaxDynamicSharedMemorySize, QKV_SMEM);
    cudaFuncSetAttribute(attn_main_kernel,
                         cudaFuncAttributeMaxDynamicSharedMemorySize, ATT_SMEM);

    prep_kernel<<<dim3(64, 3), 256>>>(Wq, Wk, Wv);
    qkv_kernel<<<128, 384, QKV_SMEM>>>(x);
    attn_main_kernel<<<1024, 128, ATT_SMEM>>>(out, should_mask);
    combine_kernel<<<512, 128>>>(out, should_mask);
}

// round 17
// speedup vs baseline: 1.0852x; 1.0242x over previous
#include <cuda_runtime.h>
#include <math.h>
#include <math_constants.h>
#include <cstdint>

// Problem shape (fixed by the reference)
constexpr int B_ = 8;
constexpr int T_ = 2048;
constexpr int E_ = 1024;
constexpr int H_ = 64;
constexpr int MT = B_ * T_;   // 16384 rows

// ---------------------------------------------------------------------------
// Device globals (no allocs allowed)
// ---------------------------------------------------------------------------
__device__ __align__(16) uint32_t g_wqh[64 * 512];
__device__ __align__(16) uint32_t g_wql[64 * 512];
__device__ __align__(16) uint32_t g_wkh[64 * 512];
__device__ __align__(16) uint32_t g_wkl[64 * 512];
__device__ __align__(16) float    g_wv [64 * 1024];   // tf32-rounded

__device__ __align__(16) uint32_t g_qbh[MT * 32];
__device__ __align__(16) uint32_t g_qbl[MT * 32];
__device__ __align__(16) uint32_t g_kbh[MT * 32];
__device__ __align__(16) uint32_t g_kbl[MT * 32];
// V^T, fp16 packed along keys: g_vt[(b*64 + h)*1024 + w] = v[b][2w..2w+1][h]
__device__ __align__(16) uint32_t g_vt [B_ * 64 * 1024];

// Split-KV scratch: 512 units (b 0..7, jq 0..15, chunk 0..3), 128 rows each
__device__ __align__(16) float g_po[512 * 8192];
__device__ float g_pm[512 * 128];
__device__ float g_pl[512 * 128];

// ===========================================================================
// Baseline-PTX helpers (all valid at compute_103)
// ===========================================================================
__device__ __forceinline__ uint32_t smem_u32(const void* p) {
    uint32_t a;
    asm("{ .reg .u64 t; cvta.to.shared.u64 t, %1; cvt.u32.u64 %0, t; }"
        : "=r"(a) : "l"(p));
    return a;
}
__device__ __forceinline__ float tf32r(float v) {
    uint32_t u;
    asm("cvt.rna.tf32.f32 %0, %1;" : "=r"(u) : "f"(v));
    return __uint_as_float(u);
}
__device__ __forceinline__ float ex2f(float x) {
    float r;
    asm("ex2.approx.f32 %0, %1;" : "=f"(r) : "f"(x));
    return r;
}
// Pack float2 -> bf16x2 hi word + bf16x2 lo word (hi = rn(v), lo = rn(v-hi))
__device__ __forceinline__ void bsplit2(float2 f, uint32_t& h, uint32_t& l) {
    asm("cvt.rn.bf16x2.f32 %0, %1, %2;" : "=r"(h) : "f"(f.y), "f"(f.x));
    float hx = __uint_as_float(h << 16);
    float hy = __uint_as_float(h & 0xffff0000u);
    asm("cvt.rn.bf16x2.f32 %0, %1, %2;" : "=r"(l) : "f"(f.y - hy), "f"(f.x - hx));
}
// Pack (hi, lo) floats -> fp16x2 word (low half = lo)
__device__ __forceinline__ uint32_t f16x2(float hi, float lo) {
    uint32_t r;
    asm("cvt.rn.f16x2.f32 %0, %1, %2;" : "=r"(r) : "f"(hi), "f"(lo));
    return r;
}
// ldmatrix: 4x (8x8 b16) tiles, no transpose
__device__ __forceinline__ void ldm4(uint32_t& r0, uint32_t& r1,
                                     uint32_t& r2, uint32_t& r3, uint32_t addr) {
    asm volatile("ldmatrix.sync.aligned.m8n8.x4.shared.b16 {%0,%1,%2,%3}, [%4];"
        : "=r"(r0), "=r"(r1), "=r"(r2), "=r"(r3) : "r"(addr));
}
// D += A(16x16) * B(16x8), bf16 inputs, fp32 accum
__device__ __forceinline__ void mma16b(float* c,
                                       uint32_t a0, uint32_t a1, uint32_t a2, uint32_t a3,
                                       uint32_t b0, uint32_t b1) {
    asm volatile(
        "mma.sync.aligned.m16n8k16.row.col.f32.bf16.bf16.f32 "
        "{%0,%1,%2,%3}, {%4,%5,%6,%7}, {%8,%9}, {%0,%1,%2,%3};"
        : "+f"(c[0]), "+f"(c[1]), "+f"(c[2]), "+f"(c[3])
        : "r"(a0), "r"(a1), "r"(a2), "r"(a3), "r"(b0), "r"(b1));
}
// D += A(16x16) * B(16x8), fp16 inputs, fp32 accum
__device__ __forceinline__ void mma16f(float* c,
                                       uint32_t a0, uint32_t a1, uint32_t a2, uint32_t a3,
                                       uint32_t b0, uint32_t b1) {
    asm volatile(
        "mma.sync.aligned.m16n8k16.row.col.f32.f16.f16.f32 "
        "{%0,%1,%2,%3}, {%4,%5,%6,%7}, {%8,%9}, {%0,%1,%2,%3};"
        : "+f"(c[0]), "+f"(c[1]), "+f"(c[2]), "+f"(c[3])
        : "r"(a0), "r"(a1), "r"(a2), "r"(a3), "r"(b0), "r"(b1));
}
// D += A(16x8) * B(8x8), tf32 inputs, fp32 accum
__device__ __forceinline__ void mma8(float* c,
                                     uint32_t a0, uint32_t a1, uint32_t a2, uint32_t a3,
                                     uint32_t b0, uint32_t b1) {
    asm volatile(
        "mma.sync.aligned.m16n8k8.row.col.f32.tf32.tf32.f32 "
        "{%0,%1,%2,%3}, {%4,%5,%6,%7}, {%8,%9}, {%0,%1,%2,%3};"
        : "+f"(c[0]), "+f"(c[1]), "+f"(c[2]), "+f"(c[3])
        : "r"(a0), "r"(a1), "r"(a2), "r"(a3), "r"(b0), "r"(b1));
}
__device__ __forceinline__ uint32_t fu(float v) { return __float_as_uint(v); }

#define CP16(d, s)  asm volatile("cp.async.ca.shared.global [%0], [%1], 16;" :: "r"(d), "l"(s))
#define CP_COMMIT() asm volatile("cp.async.commit_group;" ::: "memory")
#define CP_WAIT0()  asm volatile("cp.async.wait_group 0;" ::: "memory")
#define CP_WAIT1()  asm volatile("cp.async.wait_group 1;" ::: "memory")

// ===========================================================================
// Kernel 0: weight prep. Wq/Wk -> packed bf16 hi/lo; Wv -> tf32-rounded.
// ===========================================================================
__global__ void prep_kernel(const float* __restrict__ Wq,
                            const float* __restrict__ Wk,
                            const float* __restrict__ Wv)
{
    const int r = blockIdx.x, mat = blockIdx.y, tid = threadIdx.x;
    if (mat < 2) {
        const float* W = mat ? Wk : Wq;
        uint32_t* dh = mat ? g_wkh : g_wqh;
        uint32_t* dl = mat ? g_wkl : g_wql;
        if (tid < 256) {
            float4 f = *reinterpret_cast<const float4*>(&W[r * 1024 + 4 * tid]);
            uint32_t h0, l0, h1, l1;
            bsplit2(make_float2(f.x, f.y), h0, l0);
            bsplit2(make_float2(f.z, f.w), h1, l1);
            *reinterpret_cast<uint2*>(&dh[r * 512 + 2 * tid]) = make_uint2(h0, h1);
            *reinterpret_cast<uint2*>(&dl[r * 512 + 2 * tid]) = make_uint2(l0, l1);
        }
    } else {
        float4 f = *reinterpret_cast<const float4*>(&Wv[r * 1024 + 4 * tid]);
        float4 o = make_float4(tf32r(f.x), tf32r(f.y), tf32r(f.z), tf32r(f.w));
        *reinterpret_cast<float4*>(&g_wv[r * 1024 + 4 * tid]) = o;
    }
}

// ===========================================================================
// Kernel 1: merged QKV projection — 128 rows/CTA, grid 128, 384 threads
// (round-16 proven configuration).
// ===========================================================================
constexpr int XSTR = 40;
constexpr int WSTR = 20;
constexpr int VSTR = 36;
constexpr uint32_t OX   = 0;
constexpr uint32_t OWH0 = 20480;
constexpr uint32_t OWL0 = 25600;
constexpr uint32_t OWH1 = 30720;
constexpr uint32_t OWL1 = 35840;
constexpr uint32_t OWV  = 40960;
constexpr uint32_t QSTG = 50176;
constexpr uint32_t QKV_SMEM = 2 * QSTG;            // 100352 bytes

__global__ __launch_bounds__(384, 1) void qkv_kernel(const float* __restrict__ x)
{
    extern __shared__ char sm8[];
    const uint32_t sb = smem_u32(sm8);
    const int tid  = threadIdx.x;
    const int wid  = tid >> 5, lane = tid & 31;
    const int g = lane >> 2, c = lane & 3;
    const int mat = wid >> 2;          // 0=Q, 1=K, 2=V
    const int rb0 = (wid & 3) * 32;    // warp row base (2 sets of 16)
    const int m0  = blockIdx.x * 128;
    const uint32_t loffw = (uint32_t)(((lane & 7) * WSTR + (lane >> 3) * 4) * 4);

    auto issue = [&](int ch, int st) {
        const uint32_t s0 = sb + (uint32_t)st * QSTG;
        const int k0 = ch * 32;
        for (int i = tid; i < 2560; i += 384) {
            if (i < 1024) {
                int r = i >> 3, sg = i & 7;
                CP16(s0 + OX + (uint32_t)(r * XSTR + sg * 4) * 4,
                     (const char*)(x + (size_t)(m0 + r) * E_ + k0 + sg * 4));
            } else if (i < 2048) {
                int t = i - 1024, arr = t >> 8, u = t & 255;
                int r = u >> 2, sg = u & 3;
                const uint32_t* src =
                    (arr == 0 ? g_wqh : arr == 1 ? g_wql : arr == 2 ? g_wkh : g_wkl)
                    + r * 512 + ch * 16 + sg * 4;
                uint32_t off = (arr == 0 ? OWH0 : arr == 1 ? OWL0 : arr == 2 ? OWH1 : OWL1);
                CP16(s0 + off + (uint32_t)(r * WSTR + sg * 4) * 4, (const char*)src);
            } else {
                int t = i - 2048, r = t >> 3, sg = t & 7;
                CP16(s0 + OWV + (uint32_t)(r * VSTR + sg * 4) * 4,
                     (const char*)(g_wv + r * 1024 + k0 + sg * 4));
            }
        }
        CP_COMMIT();
    };

    float acc[2][8][4];
#pragma unroll
    for (int s = 0; s < 2; s++)
#pragma unroll
        for (int nt = 0; nt < 8; nt++)
#pragma unroll
            for (int i = 0; i < 4; i++) acc[s][nt][i] = 0.f;

    issue(0, 0);

    for (int ch = 0; ch < 32; ch++) {
        const int st = ch & 1;
        if (ch + 1 < 32) { issue(ch + 1, st ^ 1); CP_WAIT1(); } else { CP_WAIT0(); }
        __syncthreads();

        const char* stage = sm8 + (size_t)st * QSTG;
        const float* Xf = (const float*)(stage + OX);

        if (mat < 2) {
            const uint32_t KWH = sb + (uint32_t)st * QSTG + (mat ? OWH1 : OWH0);
            const uint32_t KWL = sb + (uint32_t)st * QSTG + (mat ? OWL1 : OWL0);
            uint32_t ah[2][2][4], al[2][2][4];
#pragma unroll
            for (int s = 0; s < 2; s++) {
                const int rA = rb0 + s * 16 + g;
#pragma unroll
                for (int kt = 0; kt < 2; kt++) {
                    const int cb = kt * 16 + 2 * c;
                    float2 f00 = *(const float2*)&Xf[rA * XSTR + cb];
                    float2 f10 = *(const float2*)&Xf[(rA + 8) * XSTR + cb];
                    float2 f01 = *(const float2*)&Xf[rA * XSTR + cb + 8];
                    float2 f11 = *(const float2*)&Xf[(rA + 8) * XSTR + cb + 8];
                    bsplit2(f00, ah[s][kt][0], al[s][kt][0]);
                    bsplit2(f10, ah[s][kt][1], al[s][kt][1]);
                    bsplit2(f01, ah[s][kt][2], al[s][kt][2]);
                    bsplit2(f11, ah[s][kt][3], al[s][kt][3]);
                }
            }
#pragma unroll
            for (int nt = 0; nt < 8; nt++) {
                uint32_t bh[4], bl[4];
                ldm4(bh[0], bh[1], bh[2], bh[3], KWH + (uint32_t)nt * 640 + loffw);
                ldm4(bl[0], bl[1], bl[2], bl[3], KWL + (uint32_t)nt * 640 + loffw);
#pragma unroll
                for (int s = 0; s < 2; s++) {
#pragma unroll
                    for (int kt = 0; kt < 2; kt++)
                        mma16b(acc[s][nt], ah[s][kt][0], ah[s][kt][1],
                               ah[s][kt][2], ah[s][kt][3], bh[2 * kt], bh[2 * kt + 1]);
#pragma unroll
                    for (int kt = 0; kt < 2; kt++)
                        mma16b(acc[s][nt], al[s][kt][0], al[s][kt][1],
                               al[s][kt][2], al[s][kt][3], bh[2 * kt], bh[2 * kt + 1]);
#pragma unroll
                    for (int kt = 0; kt < 2; kt++)
                        mma16b(acc[s][nt], ah[s][kt][0], ah[s][kt][1],
                               ah[s][kt][2], ah[s][kt][3], bl[2 * kt], bl[2 * kt + 1]);
                }
            }
        } else {
            const float* WV = (const float*)(stage + OWV);
#pragma unroll
            for (int kt = 0; kt < 4; kt++) {
                const int ka = kt * 8 + c;
                uint32_t aa[2][4];
#pragma unroll
                for (int s = 0; s < 2; s++) {
                    const int rA = rb0 + s * 16 + g;
                    aa[s][0] = fu(tf32r(Xf[rA * XSTR + ka]));
                    aa[s][1] = fu(tf32r(Xf[(rA + 8) * XSTR + ka]));
                    aa[s][2] = fu(tf32r(Xf[rA * XSTR + ka + 4]));
                    aa[s][3] = fu(tf32r(Xf[(rA + 8) * XSTR + ka + 4]));
                }
#pragma unroll
                for (int nt = 0; nt < 8; nt++) {
                    const int br = (nt * 8 + g) * VSTR + ka;
                    const uint32_t b0 = fu(WV[br]), b1 = fu(WV[br + 4]);
#pragma unroll
                    for (int s = 0; s < 2; s++)
                        mma8(acc[s][nt], aa[s][0], aa[s][1], aa[s][2], aa[s][3], b0, b1);
                }
            }
        }
        __syncthreads();
    }

    // ---- epilogue
    if (mat < 2) {
        uint32_t* dh = mat ? g_kbh : g_qbh;
        uint32_t* dl = mat ? g_kbl : g_qbl;
#pragma unroll
        for (int s = 0; s < 2; s++) {
            const int r0 = m0 + rb0 + s * 16 + g, r1 = r0 + 8;
#pragma unroll
            for (int nt = 0; nt < 8; nt++) {
                const int w = nt * 4 + c;
                uint32_t h, l;
                bsplit2(make_float2(acc[s][nt][0], acc[s][nt][1]), h, l);
                dh[(size_t)r0 * 32 + w] = h; dl[(size_t)r0 * 32 + w] = l;
                bsplit2(make_float2(acc[s][nt][2], acc[s][nt][3]), h, l);
                dh[(size_t)r1 * 32 + w] = h; dl[(size_t)r1 * 32 + w] = l;
            }
        }
    } else {
        float* vbuf = (float*)sm8;   // [128][68] = 34816 B, fits in stage area
#pragma unroll
        for (int s = 0; s < 2; s++) {
            const int rA = rb0 + s * 16 + g;
#pragma unroll
            for (int nt = 0; nt < 8; nt++) {
                vbuf[rA * 68 + nt * 8 + 2 * c]     = acc[s][nt][0];
                vbuf[rA * 68 + nt * 8 + 2 * c + 1] = acc[s][nt][1];
                vbuf[(rA + 8) * 68 + nt * 8 + 2 * c]     = acc[s][nt][2];
                vbuf[(rA + 8) * 68 + nt * 8 + 2 * c + 1] = acc[s][nt][3];
            }
        }
    }
    __syncthreads();
    {
        const float* vbuf = (const float*)sm8;
        const int bb = m0 >> 11;
        const int kw0 = (m0 & 2047) >> 1;
        for (int i = tid; i < 4096; i += 384) {
            int h = i >> 6, w = i & 63;
            float lo = vbuf[(2 * w) * 68 + h];
            float hi = vbuf[(2 * w + 1) * 68 + h];
            g_vt[(size_t)(bb * 64 + h) * 1024 + kw0 + w] = f16x2(hi, lo);
        }
    }
}

// ===========================================================================
// Kernel 2: flash attention, SPLIT-KV, 128-query tile.
// 512 units: u -> b = u>>6, jq = (u&63)>>2 (128-row q block), cc = u&3.
// 128 threads; each warp owns rows {s*64 + warp*16 .. +15} for s in {0,1},
// processed sequentially per iteration (K/V stage shared).
// Fully-masked sets skipped (m=-inf/l=0 partials combine to exact 0).
// ===========================================================================
constexpr uint32_t OQBH = 0;       // 128 rows x 36 u32 = 18432 B
constexpr uint32_t OQBL = 18432;
constexpr uint32_t OKBH = 36864;   // + st*9216
constexpr uint32_t OKBL = 55296;   // + st*9216
constexpr uint32_t OV   = 73728;   // + st*9216
constexpr uint32_t ATT_SMEM = 92160;

__global__ __launch_bounds__(128, 2) void attn_main_kernel(
    float* __restrict__ out, const int* __restrict__ maskp)
{
    const int mask = *maskp;
    const uint32_t u = blockIdx.x;
    const int b  = u >> 6;
    const int jq = (u & 63) >> 2;
    const int cc = u & 3;
    if (mask && 8 * cc > 2 * jq + 1) return;

    extern __shared__ char sma[];
    const uint32_t sb = smem_u32(sma);
    const int tid  = threadIdx.x;
    const int warp = tid >> 5, lane = tid & 31;
    const int g = lane >> 2, c = lane & 3;
    const int wb = warp * 16;
    const uint32_t loffa = (uint32_t)(((lane & 7) * 36 + (lane >> 3) * 4) * 4);
    const uint32_t qoff = (uint32_t)(((wb + (lane & 7) + ((lane >> 3) & 1) * 8) * 36
                                      + (lane >> 4) * 4) * 4);

    const int t0 = jq * 128;
    const int j0 = 8 * cc;
    const int j1 = mask ? min(8 * cc + 7, 2 * jq + 1) : 8 * cc + 7;
    const size_t roff = (size_t)b * T_;

    auto issue_kv = [&](int j, int st) {
        const int s0r = j * 64;
        const uint32_t kb = sb + OKBH + (uint32_t)st * 9216;
        const uint32_t kl = sb + OKBL + (uint32_t)st * 9216;
        const uint32_t vv = sb + OV   + (uint32_t)st * 9216;
        for (int i = tid; i < 1536; i += 128) {
            if (i < 512) {
                int r = i >> 3, sg = i & 7;
                CP16(kb + (uint32_t)(r * 36 + sg * 4) * 4,
                     (const char*)(g_kbh + (roff + s0r + r) * 32 + sg * 4));
            } else if (i < 1024) {
                int t = i - 512, r = t >> 3, sg = t & 7;
                CP16(kl + (uint32_t)(r * 36 + sg * 4) * 4,
                     (const char*)(g_kbl + (roff + s0r + r) * 32 + sg * 4));
            } else {
                int t = i - 1024, h = t >> 3, sg = t & 7;
                CP16(vv + (uint32_t)(h * 36 + sg * 4) * 4,
                     (const char*)(g_vt + (size_t)(b * 64 + h) * 1024
                                   + (s0r >> 1) + sg * 4));
            }
        }
        CP_COMMIT();
    };

    // ---- prologue: Q (128 rows, hi+lo) + first K/V stage
    for (int i = tid; i < 2048; i += 128) {
        int arr = i >> 10, t = i & 1023, r = t >> 3, sg = t & 7;
        const uint32_t* src = (arr ? g_qbl : g_qbh) + (roff + t0 + r) * 32 + sg * 4;
        CP16(sb + (arr ? OQBL : OQBH) + (uint32_t)(r * 36 + sg * 4) * 4,
             (const char*)src);
    }
    issue_kv(j0, 0);

    CP_WAIT0();
    __syncthreads();

    const float RS = 8.0f * 1.4426950408889634f;   // log2 domain

    float rm[2][2] = {{-CUDART_INF_F, -CUDART_INF_F},
                      {-CUDART_INF_F, -CUDART_INF_F}};
    float rl[2][2] = {{0.f, 0.f}, {0.f, 0.f}};
    float o[2][8][4];
#pragma unroll
    for (int s = 0; s < 2; s++)
#pragma unroll
        for (int nt = 0; nt < 8; nt++)
#pragma unroll
            for (int i = 0; i < 4; i++) o[s][nt][i] = 0.f;

    for (int j = j0; j <= j1; j++) {
        const int st = (j - j0) & 1;
        if (j + 1 <= j1) { issue_kv(j + 1, st ^ 1); CP_WAIT1(); } else { CP_WAIT0(); }
        __syncthreads();

        const uint32_t KBH = sb + OKBH + (uint32_t)st * 9216;
        const uint32_t KBL = sb + OKBL + (uint32_t)st * 9216;
        const uint32_t VB  = sb + OV   + (uint32_t)st * 9216;
        const int s0 = j * 64;

#pragma unroll
        for (int s = 0; s < 2; s++) {
            const int rbase = t0 + s * 64 + wb;
            if (mask && s0 > rbase + 15) continue;   // fully masked set

            // ---- Q fragments for this set (transient registers)
            uint32_t qh[4][4], ql[4][4];
#pragma unroll
            for (int kt = 0; kt < 4; kt++) {
                ldm4(qh[kt][0], qh[kt][1], qh[kt][2], qh[kt][3],
                     sb + OQBH + qoff + (uint32_t)(s * 9216 + kt * 32));
                ldm4(ql[kt][0], ql[kt][1], ql[kt][2], ql[kt][3],
                     sb + OQBL + qoff + (uint32_t)(s * 9216 + kt * 32));
            }

            float sacc[8][4];
#pragma unroll
            for (int nt = 0; nt < 8; nt++)
#pragma unroll
                for (int i = 0; i < 4; i++) sacc[nt][i] = 0.f;

#pragma unroll
            for (int nt = 0; nt < 8; nt++) {
                uint32_t bh[8], bl[8];
                ldm4(bh[0], bh[1], bh[2], bh[3], KBH + (uint32_t)nt * 1152 + loffa);
                ldm4(bh[4], bh[5], bh[6], bh[7], KBH + (uint32_t)nt * 1152 + loffa + 64);
                ldm4(bl[0], bl[1], bl[2], bl[3], KBL + (uint32_t)nt * 1152 + loffa);
                ldm4(bl[4], bl[5], bl[6], bl[7], KBL + (uint32_t)nt * 1152 + loffa + 64);
#pragma unroll
                for (int kt = 0; kt < 4; kt++)
                    mma16b(sacc[nt], qh[kt][0], qh[kt][1], qh[kt][2], qh[kt][3],
                           bh[2 * kt], bh[2 * kt + 1]);
#pragma unroll
                for (int kt = 0; kt < 4; kt++)
                    mma16b(sacc[nt], ql[kt][0], ql[kt][1], ql[kt][2], ql[kt][3],
                           bh[2 * kt], bh[2 * kt + 1]);
#pragma unroll
                for (int kt = 0; kt < 4; kt++)
                    mma16b(sacc[nt], qh[kt][0], qh[kt][1], qh[kt][2], qh[kt][3],
                           bl[2 * kt], bl[2 * kt + 1]);
            }

            const bool diag = (mask != 0) && (s0 + 63 > rbase);
#pragma unroll
            for (int nt = 0; nt < 8; nt++) {
#pragma unroll
                for (int e = 0; e < 4; e++) {
                    const int sg = s0 + nt * 8 + 2 * c + (e & 1);
                    const int tg = rbase + g + (e >> 1) * 8;
                    float v = sacc[nt][e] * RS;
                    if (diag && sg > tg) v = -CUDART_INF_F;
                    sacc[nt][e] = v;
                }
            }

            float alpha[2];
#pragma unroll
            for (int i = 0; i < 2; i++) {
                float m = -CUDART_INF_F;
#pragma unroll
                for (int nt = 0; nt < 8; nt++)
                    m = fmaxf(m, fmaxf(sacc[nt][2 * i], sacc[nt][2 * i + 1]));
                m = fmaxf(m, __shfl_xor_sync(0xffffffffu, m, 1));
                m = fmaxf(m, __shfl_xor_sync(0xffffffffu, m, 2));
                const float mnew = fmaxf(rm[s][i], m);
                alpha[i] = ex2f(rm[s][i] - mnew);
                float sum = 0.f;
#pragma unroll
                for (int nt = 0; nt < 8; nt++) {
                    float p0 = ex2f(sacc[nt][2 * i]     - mnew);
                    float p1 = ex2f(sacc[nt][2 * i + 1] - mnew);
                    sacc[nt][2 * i] = p0; sacc[nt][2 * i + 1] = p1;
                    sum += p0 + p1;
                }
                sum += __shfl_xor_sync(0xffffffffu, sum, 1);
                sum += __shfl_xor_sync(0xffffffffu, sum, 2);
                rl[s][i] = rl[s][i] * alpha[i] + sum;
                rm[s][i] = mnew;
            }

            uint32_t aa[4][4];
#pragma unroll
            for (int kt = 0; kt < 4; kt++) {
                aa[kt][0] = f16x2(sacc[2 * kt][1],     sacc[2 * kt][0]);
                aa[kt][1] = f16x2(sacc[2 * kt][3],     sacc[2 * kt][2]);
                aa[kt][2] = f16x2(sacc[2 * kt + 1][1], sacc[2 * kt + 1][0]);
                aa[kt][3] = f16x2(sacc[2 * kt + 1][3], sacc[2 * kt + 1][2]);
            }
#pragma unroll
            for (int nt = 0; nt < 8; nt++) {
                o[s][nt][0] *= alpha[0]; o[s][nt][1] *= alpha[0];
                o[s][nt][2] *= alpha[1]; o[s][nt][3] *= alpha[1];
            }
#pragma unroll
            for (int nt = 0; nt < 8; nt++) {
                uint32_t vt[8];
                ldm4(vt[0], vt[1], vt[2], vt[3], VB + (uint32_t)nt * 1152 + loffa);
                ldm4(vt[4], vt[5], vt[6], vt[7], VB + (uint32_t)nt * 1152 + loffa + 64);
#pragma unroll
                for (int kt = 0; kt < 4; kt++)
                    mma16f(o[s][nt], aa[kt][0], aa[kt][1], aa[kt][2], aa[kt][3],
                           vt[2 * kt], vt[2 * kt + 1]);
            }
        }
        __syncthreads();
    }

    if (mask && jq < 4) {
        // single-chunk q-block: normalize and write output directly
#pragma unroll
        for (int s = 0; s < 2; s++) {
            const float inv0 = 1.0f / rl[s][0], inv1 = 1.0f / rl[s][1];
            const size_t r0o = roff + t0 + s * 64 + wb + g;
#pragma unroll
            for (int nt = 0; nt < 8; nt++) {
                *(float2*)&out[r0o * H_ + nt * 8 + 2 * c] =
                    make_float2(o[s][nt][0] * inv0, o[s][nt][1] * inv0);
                *(float2*)&out[(r0o + 8) * H_ + nt * 8 + 2 * c] =
                    make_float2(o[s][nt][2] * inv1, o[s][nt][3] * inv1);
            }
        }
        return;
    }

    // ---- write partial O (unnormalized), m, l
    float* po = g_po + (size_t)u * 8192;
#pragma unroll
    for (int s = 0; s < 2; s++) {
        const int r0 = s * 64 + wb + g;
#pragma unroll
        for (int nt = 0; nt < 8; nt++) {
            *(float2*)&po[r0 * 64 + nt * 8 + 2 * c] =
                make_float2(o[s][nt][0], o[s][nt][1]);
            *(float2*)&po[(r0 + 8) * 64 + nt * 8 + 2 * c] =
                make_float2(o[s][nt][2], o[s][nt][3]);
        }
        if (c == 0) {
            g_pm[u * 128 + r0] = rm[s][0];     g_pl[u * 128 + r0] = rl[s][0];
            g_pm[u * 128 + r0 + 8] = rm[s][1]; g_pl[u * 128 + r0 + 8] = rl[s][1];
        }
    }
}

// ===========================================================================
// Kernel 3: split-KV combine. 512 CTAs (b, jq16, row-quarter), 128 threads.
// ===========================================================================
__global__ __launch_bounds__(128) void combine_kernel(
    float* __restrict__ out, const int* __restrict__ maskp)
{
    const int bid = blockIdx.x;
    const int sub = bid & 3;
    const int blk = bid >> 2;          // 0..127
    const int b = blk >> 4, jq = blk & 15;
    const int mask = *maskp;
    if (mask && jq < 4) return;        // written directly by attn_main
    const int nc = mask ? ((2 * jq + 1) >> 3) + 1 : 4;
    const int t = threadIdx.x;
    const int r = sub * 32 + (t >> 2);    // row 0..127
    const int q = (t & 3) * 16;           // col base
    const uint32_t ub = (uint32_t)(b * 64 + jq * 4);

    float m[4], l[4];
    float M = -CUDART_INF_F;
#pragma unroll 4
    for (int i = 0; i < nc; i++) {
        m[i] = g_pm[(ub + i) * 128 + r];
        l[i] = g_pl[(ub + i) * 128 + r];
        M = fmaxf(M, m[i]);
    }
    float L = 0.f, w[4];
#pragma unroll 4
    for (int i = 0; i < nc; i++) {
        w[i] = ex2f(m[i] - M);
        L += l[i] * w[i];
    }

    float4 acc[4];
#pragma unroll
    for (int k = 0; k < 4; k++) acc[k] = make_float4(0.f, 0.f, 0.f, 0.f);
#pragma unroll 4
    for (int i = 0; i < nc; i++) {
        const float* src = g_po + (size_t)(ub + i) * 8192 + r * 64 + q;
        const float wi = w[i];
#pragma unroll
        for (int k = 0; k < 4; k++) {
            float4 v = *(const float4*)&src[k * 4];
            acc[k].x += wi * v.x; acc[k].y += wi * v.y;
            acc[k].z += wi * v.z; acc[k].w += wi * v.w;
        }
    }
    const float inv = 1.0f / L;
    float* dst = out + ((size_t)b * T_ + jq * 128 + r) * H_ + q;
#pragma unroll
    for (int k = 0; k < 4; k++) {
        float4 v = make_float4(acc[k].x * inv, acc[k].y * inv,
                               acc[k].z * inv, acc[k].w * inv);
        *(float4*)&dst[k * 4] = v;
    }
}

// ---------------------------------------------------------------------------
extern "C" void kernel_launch(void* const* d_in, const int* in_sizes, int n_in,
                              void* d_out, int out_size)
{
    const float* x  = (const float*)d_in[0];
    const float* Wq = (const float*)d_in[1];
    const float* Wk = (const float*)d_in[2];
    const float* Wv = (const float*)d_in[3];
    const int* should_mask = (const int*)d_in[4];
    float* out = (float*)d_out;

    cudaFuncSetAttribute(qkv_kernel,
                         cudaFuncAttributeMaxDynamicSharedMemorySize, QKV_SMEM);
    cudaFuncSetAttribute(attn_main_kernel,
                         cudaFuncAttributeMaxDynamicSharedMemorySize, ATT_SMEM);

    prep_kernel<<<dim3(64, 3), 256>>>(Wq, Wk, Wv);
    qkv_kernel<<<128, 384, QKV_SMEM>>>(x);
    attn_main_kernel<<<512, 128, ATT_SMEM>>>(out, should_mask);
    combine_kernel<<<512, 128>>>(out, should_mask);
}